// round 6
// baseline (speedup 1.0000x reference)
#include <cuda_runtime.h>
#include <cuda_bf16.h>

#define NC 50000
#define BATCH 128
#define ROWS 768                 // 6 parts * 128
#define DIM 1536                 // 6 * 256
#define N4 12500                 // float4 per row
#define KTILE 128
#define NTILE (DIM / KTILE)      // 12

// ---------------- device scratch (no cudaMalloc allowed) ----------------
__device__ float g_ce[ROWS];            // ce + 0.1*adv_nll per row
__device__ float g_klw[ROWS];
__device__ float g_tri[2 * BATCH];
__device__ float g_F[BATCH * DIM];      // normalized feat rows, fp32
__device__ __align__(16) __nv_bfloat16 g_TtB[DIM * 256]; // transposed targets
__device__ float g_n2[256];

__device__ __forceinline__ float ex2(float v) {
    float r;
    asm("ex2.approx.ftz.f32 %0, %1;" : "=f"(r) : "f"(v));
    return r;
}
__device__ __forceinline__ void cpa16(unsigned dst, const void* src) {
    asm volatile("cp.async.ca.shared.global [%0], [%1], 16;" :: "r"(dst), "l"(src));
}

// ============================================================
// prep: normalize concatenated part features; fp32 rows + bf16 transpose.
// ============================================================
__global__ __launch_bounds__(256) void prep_kernel(
    const float* __restrict__ idf, const float* __restrict__ gf)
{
    const int tid = threadIdx.x;
    const int lane = tid & 31, wid = tid >> 5;
    const unsigned full = 0xffffffffu;

    int j = blockIdx.x;                 // 0..255
    const float* src = (j < BATCH) ? idf : gf;
    int b = j & (BATCH - 1);

    float v[6];
    float sq = 0.f;
#pragma unroll
    for (int p = 0; p < 6; p++) {
        float x = src[(size_t)(p * BATCH + b) * 256 + tid];
        v[p] = x;
        sq = fmaf(x, x, sq);
    }
#pragma unroll
    for (int off = 16; off; off >>= 1) sq += __shfl_down_sync(full, sq, off);
    __shared__ float wsum[8];
    if (lane == 0) wsum[wid] = sq;
    __syncthreads();
    float tot = 0.f;
#pragma unroll
    for (int w = 0; w < 8; w++) tot += wsum[w];
    float rn = rsqrtf(tot);
#pragma unroll
    for (int p = 0; p < 6; p++) {
        int d = p * 256 + tid;
        float nv = v[p] * rn;
        g_TtB[(size_t)d * 256 + j] = __float2bfloat16_rn(nv);
        if (j < BATCH) g_F[(size_t)b * DIM + d] = nv;
    }
    if (tid == 0) g_n2[j] = tot * rn * rn;
}

// ============================================================
// row: per-row dual-temperature softmax stats; branchless, 8 batched
// LDG.128/iter, per-lane f4 accumulators, reg cap via launch_bounds(256,3).
// ============================================================
__global__ __launch_bounds__(256, 3) void row_kernel(
    const float* __restrict__ logits, const float* __restrict__ soft,
    const float* __restrict__ ew,     const int*   __restrict__ labels,
    const float* __restrict__ adv,    const int*   __restrict__ mod)
{
    const int tid = threadIdx.x;
    const int lane = tid & 31, wid = tid >> 5;
    const unsigned full = 0xffffffffu;

    const int r = blockIdx.x;
    const float4* lg4 = (const float4*)(logits + (size_t)r * NC);
    const float4* sf4 = (const float4*)(soft   + (size_t)r * NC);
    const float C = 0.48089834696298783f;   // log2(e)/3

    float4 vs1 = {0,0,0,0}, vs2 = {0,0,0,0}, vsx = {0,0,0,0};
    float4 vss = {0,0,0,0}, vssx = {0,0,0,0}, vssl = {0,0,0,0};

#define ACC(xx, sv_, L)                                               \
    {   float x = xx, sv = sv_;                                       \
        vsx.L += x;  vss.L += sv;                                     \
        vssx.L = fmaf(sv, x, vssx.L);                                 \
        vssl.L = fmaf(sv, __log2f(fmaxf(sv, 1e-38f)), vssl.L);        \
        float e = ex2(x * C);                                         \
        vs2.L += e;                                                   \
        vs1.L = fmaf(e * e, e, vs1.L); }
#define LANE4(x4, t4) ACC(x4.x, t4.x, x) ACC(x4.y, t4.y, y) \
                      ACC(x4.z, t4.z, z) ACC(x4.w, t4.w, w)

    int i = tid;
    for (; i + 768 < N4; i += 1024) {
        float4 x0 = __ldcs(lg4 + i);
        float4 x1 = __ldcs(lg4 + i + 256);
        float4 x2 = __ldcs(lg4 + i + 512);
        float4 x3 = __ldcs(lg4 + i + 768);
        float4 t0 = __ldcs(sf4 + i);
        float4 t1 = __ldcs(sf4 + i + 256);
        float4 t2 = __ldcs(sf4 + i + 512);
        float4 t3 = __ldcs(sf4 + i + 768);
        LANE4(x0, t0) LANE4(x1, t1) LANE4(x2, t2) LANE4(x3, t3)
    }
    for (; i < N4; i += 256) {
        float4 x0 = __ldcs(lg4 + i);
        float4 t0 = __ldcs(sf4 + i);
        LANE4(x0, t0)
    }
#undef LANE4
#undef ACC

    float s1  = (vs1.x + vs1.y) + (vs1.z + vs1.w);
    float s2  = (vs2.x + vs2.y) + (vs2.z + vs2.w);
    float sx  = (vsx.x + vsx.y) + (vsx.z + vsx.w);
    float ssv = (vss.x + vss.y) + (vss.z + vss.w);
    float ssx = (vssx.x + vssx.y) + (vssx.z + vssx.w);
    float ssl = (vssl.x + vssl.y) + (vssl.z + vssl.w);

#pragma unroll
    for (int off = 16; off; off >>= 1) {
        s1  += __shfl_down_sync(full, s1,  off);
        s2  += __shfl_down_sync(full, s2,  off);
        sx  += __shfl_down_sync(full, sx,  off);
        ssv += __shfl_down_sync(full, ssv, off);
        ssx += __shfl_down_sync(full, ssx, off);
        ssl += __shfl_down_sync(full, ssl, off);
    }

    __shared__ float sm[6][8];
    if (lane == 0) {
        sm[0][wid] = s1;  sm[1][wid] = s2;  sm[2][wid] = sx;
        sm[3][wid] = ssv; sm[4][wid] = ssx; sm[5][wid] = ssl;
    }
    __syncthreads();

    if (tid == 0) {
        s1 = 0.f; s2 = 0.f; sx = 0.f; ssv = 0.f; ssx = 0.f; ssl = 0.f;
#pragma unroll
        for (int w = 0; w < 8; w++) {
            s1 += sm[0][w]; s2 += sm[1][w]; sx += sm[2][w];
            ssv += sm[3][w]; ssx += sm[4][w]; ssl += sm[5][w];
        }
        float logZ1 = __logf(s1);
        float logZ2 = __logf(s2);

        int   b   = r & (BATCH - 1);
        int   lab = labels[b];
        float xl  = logits[(size_t)r * NC + lab];
        float ce  = logZ1 - 0.9f * xl - 0.1f * sx * (1.f / (float)NC);

        float l0 = adv[2 * r], l1 = adv[2 * r + 1];
        float mm = fmaxf(l0, l1);
        float lse = mm + __logf(__expf(l0 - mm) + __expf(l1 - mm));
        float anll = lse - (mod[b] ? l1 : l0);
        g_ce[r] = ce + 0.1f * anll;

        float kl = ssl * 0.6931471805599453f - ssx * (1.f / 3.f) + logZ2 * ssv;
        g_klw[r] = fminf(kl, 5.0f) * ew[r];
    }
}

// ============================================================
// dist: 128 blocks = (64 anchor-pairs) x (2 target halves).
// 2-stage cp.async pipeline: tile t+1 streams from L2 while tile t computes
// from smem. Batch-hard mining epilogue. Runs CONCURRENTLY with row_kernel.
// ============================================================
__global__ __launch_bounds__(256) void dist_kernel(const int* __restrict__ labels)
{
    __shared__ __align__(16) __nv_bfloat16 Ts[2][KTILE][128];  // 64 KB
    __shared__ __align__(16) float As[2][2][KTILE];            // 2 KB
    __shared__ float red[8][2][128];                           // 8 KB
    __shared__ float wmax[2][8], wmin[2][8];

    const int tid = threadIdx.x;
    const int lane = tid & 31, wid = tid >> 5;
    const unsigned full = 0xffffffffu;

    int p  = blockIdx.x >> 1;
    int h  = blockIdx.x & 1;
    int i0 = p * 2;

    unsigned ts_base = (unsigned)__cvta_generic_to_shared(Ts);
    unsigned as_base = (unsigned)__cvta_generic_to_shared(As);

    const int trow = tid >> 1;               // 0..127: k row within tile
    const int tcol = (tid & 1) * 128;        // byte offset within 256B half-row

    // stage loader for tile index t into ring slot (t & 1)
    auto stage = [&](int t) {
        int k0 = t * KTILE;
        int st = t & 1;
        const char* gsrc = (const char*)g_TtB
                         + (size_t)(k0 + trow) * 512 + h * 256 + tcol;
        unsigned sdst = ts_base + st * (KTILE * 256) + trow * 256 + tcol;
#pragma unroll
        for (int c8 = 0; c8 < 8; c8++)
            cpa16(sdst + c8 * 16, gsrc + c8 * 16);
        if (tid < 64) {
            int a  = tid >> 5;
            int ch = tid & 31;
            const char* asrc = (const char*)(g_F + (size_t)(i0 + a) * DIM + k0)
                             + ch * 16;
            cpa16(as_base + (st * 2 + a) * (KTILE * 4) + ch * 16, asrc);
        }
        asm volatile("cp.async.commit_group;");
    };

    float c00 = 0.f, c01 = 0.f, c02 = 0.f, c03 = 0.f;
    float c10 = 0.f, c11 = 0.f, c12 = 0.f, c13 = 0.f;

    stage(0);
#pragma unroll 1
    for (int t = 0; t < NTILE; t++) {
        if (t + 1 < NTILE) {
            stage(t + 1);
            asm volatile("cp.async.wait_group 1;" ::: "memory");
        } else {
            asm volatile("cp.async.wait_group 0;" ::: "memory");
        }
        __syncthreads();

        int st = t & 1;
        int kl0 = wid * 16;
#pragma unroll
        for (int kk = 0; kk < 16; kk++) {
            int k = kl0 + kk;
            uint2 tv = *(const uint2*)((const char*)Ts[st] + k * 256 + lane * 8);
            float f0 = __uint_as_float(tv.x << 16);
            float f1 = __uint_as_float(tv.x & 0xffff0000u);
            float f2 = __uint_as_float(tv.y << 16);
            float f3 = __uint_as_float(tv.y & 0xffff0000u);
            float A0 = As[st][0][k], A1 = As[st][1][k];
            c00 = fmaf(A0, f0, c00); c01 = fmaf(A0, f1, c01);
            c02 = fmaf(A0, f2, c02); c03 = fmaf(A0, f3, c03);
            c10 = fmaf(A1, f0, c10); c11 = fmaf(A1, f1, c11);
            c12 = fmaf(A1, f2, c12); c13 = fmaf(A1, f3, c13);
        }
        __syncthreads();   // compute done before this slot is re-staged
    }

    ((float4*)red[wid][0])[lane] = make_float4(c00, c01, c02, c03);
    ((float4*)red[wid][1])[lane] = make_float4(c10, c11, c12, c13);
    __syncthreads();

    int a  = tid >> 7;
    int jl = tid & 127;
    int ia = i0 + a;
    int jglob = h * 128 + jl;

    float dot = 0.f;
#pragma unroll
    for (int sl = 0; sl < 8; sl++) dot += red[sl][a][jl];
    float sqv = g_n2[ia] + g_n2[jglob] - 2.f * dot;
    float dj  = sqrtf(fmaxf(sqv, 0.f) + 1e-12f);

    bool eq  = (labels[ia] == labels[jl]);
    bool pos = h ? eq : (eq && (jl != ia));
    float apv = pos   ? dj : -1e30f;
    float anv = (!eq) ? dj :  1e30f;
#pragma unroll
    for (int off = 16; off; off >>= 1) {
        apv = fmaxf(apv, __shfl_down_sync(full, apv, off));
        anv = fminf(anv, __shfl_down_sync(full, anv, off));
    }
    if (lane == 0) { wmax[a][wid & 3] = apv; wmin[a][wid & 3] = anv; }
    __syncthreads();

    if ((tid & 127) == 0) {
        float apm = fmaxf(fmaxf(wmax[a][0], wmax[a][1]), fmaxf(wmax[a][2], wmax[a][3]));
        float anm = fminf(fminf(wmin[a][0], wmin[a][1]), fminf(wmin[a][2], wmin[a][3]));
        float dap = (apm > -1e29f) ? apm : 0.f;
        float dan = (anm <  1e29f) ? anm : 1e6f;
        g_tri[h * BATCH + ia] = fmaxf(dap - dan + 0.3f, 0.f);
    }
}

// ============================================================
// final: deterministic scalar reduce.
// ============================================================
__global__ __launch_bounds__(256) void final_kernel(
    const int* __restrict__ epoch_p, float* __restrict__ out)
{
    const int tid = threadIdx.x;
    const int lane = tid & 31, wid = tid >> 5;
    const unsigned full = 0xffffffffu;

    float ceA = 0.f, klwA = 0.f, tri0 = 0.f, tri1 = 0.f;
    for (int r = tid; r < ROWS; r += 256) {
        ceA  += g_ce[r];
        klwA += g_klw[r];
    }
    if (tid < BATCH) { tri0 = g_tri[tid]; tri1 = g_tri[BATCH + tid]; }

#pragma unroll
    for (int off = 16; off; off >>= 1) {
        ceA  += __shfl_down_sync(full, ceA,  off);
        klwA += __shfl_down_sync(full, klwA, off);
        tri0 += __shfl_down_sync(full, tri0, off);
        tri1 += __shfl_down_sync(full, tri1, off);
    }
    __shared__ float fm[4][8];
    if (lane == 0) {
        fm[0][wid] = ceA; fm[1][wid] = klwA; fm[2][wid] = tri0; fm[3][wid] = tri1;
    }
    __syncthreads();

    if (tid == 0) {
        float ceT = 0.f, klwT = 0.f, t0 = 0.f, t1 = 0.f;
#pragma unroll
        for (int w = 0; w < 8; w++) {
            ceT += fm[0][w]; klwT += fm[1][w]; t0 += fm[2][w]; t1 += fm[3][w];
        }
        float L_idadv = ceT * (1.f / (float)ROWS);   // includes 0.1*L_adv
        float L_tri   = (t0 + 0.5f * t1) * (1.f / (float)BATCH);
        float L_graph = (epoch_p[0] >= 20) ? klwT * (9.f / (float)ROWS) : 0.f;
        out[0] = L_idadv + L_tri + 0.1f * L_graph;
    }
}

// ============================================================
extern "C" void kernel_launch(void* const* d_in, const int* in_sizes, int n_in,
                              void* d_out, int out_size)
{
    const float* id_logits     = (const float*)d_in[0];
    const float* id_features   = (const float*)d_in[1];
    const float* gray_features = (const float*)d_in[2];
    const float* soft_labels   = (const float*)d_in[3];
    const float* entropy_w     = (const float*)d_in[4];
    const float* adv_logits    = (const float*)d_in[5];
    const int*   labels        = (const int*)d_in[6];
    const int*   mod_labels    = (const int*)d_in[7];
    const int*   epoch         = (const int*)d_in[8];

    // one-time resources (no device-memory allocation involved)
    static cudaStream_t s1 = nullptr;
    static cudaEvent_t  ev_prep = nullptr, ev_dist = nullptr;
    if (!s1) {
        cudaStreamCreateWithFlags(&s1, cudaStreamNonBlocking);
        cudaEventCreateWithFlags(&ev_prep, cudaEventDisableTiming);
        cudaEventCreateWithFlags(&ev_dist, cudaEventDisableTiming);
    }

    // main stream: prep -> row ; forked stream: dist (after prep) ; join -> final
    prep_kernel<<<256, 256>>>(id_features, gray_features);
    cudaEventRecord(ev_prep, 0);

    cudaStreamWaitEvent(s1, ev_prep, 0);
    dist_kernel<<<BATCH, 256, 0, s1>>>(labels);
    cudaEventRecord(ev_dist, s1);

    row_kernel<<<ROWS, 256>>>(id_logits, soft_labels, entropy_w, labels,
                              adv_logits, mod_labels);

    cudaStreamWaitEvent(0, ev_dist, 0);
    final_kernel<<<1, 256>>>(epoch, (float*)d_out);
}